// round 2
// baseline (speedup 1.0000x reference)
#include <cuda_runtime.h>
#include <cuda_bf16.h>
#include <math.h>

// Problem constants (GCN_83081847374393)
#define N_SRC0   50000
#define N_DST0V  20000
#define N_DST1   5000
#define EMB      128
#define HID      256
#define OUTD     16
#define WORDS_PER_NODE 50   // (10 * 5)

// -------- scratch (device globals; no allocation allowed) --------
__device__ float g_x0  [(size_t)N_SRC0  * EMB];   // 25.6 MB  (already deg_out0-scaled)
__device__ float g_agg0[(size_t)N_DST0V * EMB];   // 10.24 MB
__device__ float g_h1  [(size_t)N_DST0V * HID];   // 20.48 MB (already deg_out1-scaled)
__device__ float g_agg1[(size_t)N_DST1  * HID];   //  5.12 MB
__device__ int   g_deg_out0[N_SRC0];
__device__ int   g_deg_in0 [N_DST0V];
__device__ int   g_deg_out1[N_DST0V];
__device__ int   g_deg_in1 [N_DST1];

// ---------------- zero scratch accumulators ----------------
__global__ void k_zero() {
    int i = blockIdx.x * blockDim.x + threadIdx.x;
    if (i < N_DST0V * EMB) g_agg0[i] = 0.0f;
    if (i < N_DST1 * HID)  g_agg1[i] = 0.0f;
    if (i < N_SRC0)        g_deg_out0[i] = 0;
    if (i < N_DST0V)       { g_deg_in0[i] = 0; g_deg_out1[i] = 0; }
    if (i < N_DST1)        g_deg_in1[i] = 0;
}

// ---------------- degree counting ----------------
__global__ void k_degrees(const int* __restrict__ src0, const int* __restrict__ dst0, int e0,
                          const int* __restrict__ src1, const int* __restrict__ dst1, int e1) {
    int i = blockIdx.x * blockDim.x + threadIdx.x;
    if (i < e0) {
        atomicAdd(&g_deg_out0[src0[i]], 1);
        atomicAdd(&g_deg_in0 [dst0[i]], 1);
    }
    if (i < e1) {
        atomicAdd(&g_deg_out1[src1[i]], 1);
        atomicAdd(&g_deg_in1 [dst1[i]], 1);
    }
}

// ---------------- embedding gather + mean + deg_out0 scaling ----------------
// one warp per node; lane handles 4 consecutive floats (float4)
__global__ void k_embed(const int* __restrict__ uw, const float* __restrict__ table, int n_nodes) {
    int warp = (blockIdx.x * blockDim.x + threadIdx.x) >> 5;
    int lane = threadIdx.x & 31;
    if (warp >= n_nodes) return;
    const int* w = uw + (size_t)warp * WORDS_PER_NODE;
    float ax = 0.f, ay = 0.f, az = 0.f, aw = 0.f;
#pragma unroll 5
    for (int j = 0; j < WORDS_PER_NODE; j++) {
        int idx = __ldg(&w[j]);                       // warp-uniform -> 1 sector
        const float4 v = *(const float4*)(table + (size_t)idx * EMB + lane * 4);
        ax += v.x; ay += v.y; az += v.z; aw += v.w;
    }
    float sc = rsqrtf(fmaxf((float)g_deg_out0[warp], 1.0f)) * (1.0f / WORDS_PER_NODE);
    float4 o; o.x = ax * sc; o.y = ay * sc; o.z = az * sc; o.w = aw * sc;
    *(float4*)(g_x0 + (size_t)warp * EMB + lane * 4) = o;
}

// ---------------- scatter-add layer 0 (128-wide rows) ----------------
// one warp per edge; lane does a float4 read + 4 scalar atomicAdds
__global__ void k_scatter0(const int* __restrict__ src0, const int* __restrict__ dst0, int e0) {
    int e    = (blockIdx.x * blockDim.x + threadIdx.x) >> 5;
    int lane = threadIdx.x & 31;
    if (e >= e0) return;
    int s = src0[e];
    int d = dst0[e];
    const float4 v = *(const float4*)(g_x0 + (size_t)s * EMB + lane * 4);
    float* dp = g_agg0 + (size_t)d * EMB + lane * 4;
    atomicAdd(dp + 0, v.x);
    atomicAdd(dp + 1, v.y);
    atomicAdd(dp + 2, v.z);
    atomicAdd(dp + 3, v.w);
}

// ---------------- GEMM1: h1 = relu((agg0*rsqrt(deg_in0)) @ W1 + b1) * rsqrt(deg_out1) ----------
// block = 256 threads = 1 col each over HID=256; TILE_R=16 rows per block
#define TILE_R 16
__global__ void __launch_bounds__(256) k_gemm1(const float* __restrict__ W1,
                                               const float* __restrict__ b1) {
    __shared__ float s_a[TILE_R][EMB];
    __shared__ float s_sin[TILE_R];   // rsqrt(deg_in0)
    __shared__ float s_sout[TILE_R];  // rsqrt(deg_out1)
    int tid  = threadIdx.x;
    int row0 = blockIdx.x * TILE_R;

    if (tid < TILE_R) {
        s_sin [tid] = rsqrtf(fmaxf((float)g_deg_in0 [row0 + tid], 1.0f));
        s_sout[tid] = rsqrtf(fmaxf((float)g_deg_out1[row0 + tid], 1.0f));
    }
    __syncthreads();

    // load + scale A tile: 16*128 = 2048 floats, 8 per thread
#pragma unroll
    for (int i = tid; i < TILE_R * EMB; i += 256) {
        int r = i >> 7, k = i & 127;
        s_a[r][k] = g_agg0[(size_t)(row0 + r) * EMB + k] * s_sin[r];
    }
    __syncthreads();

    int c = tid;  // 0..255 output column
    float acc[TILE_R];
#pragma unroll
    for (int r = 0; r < TILE_R; r++) acc[r] = 0.0f;

#pragma unroll 4
    for (int k4 = 0; k4 < EMB / 4; k4++) {
        float w0 = W1[(k4 * 4 + 0) * HID + c];
        float w1 = W1[(k4 * 4 + 1) * HID + c];
        float w2 = W1[(k4 * 4 + 2) * HID + c];
        float w3 = W1[(k4 * 4 + 3) * HID + c];
#pragma unroll
        for (int r = 0; r < TILE_R; r++) {
            float4 a = *(const float4*)&s_a[r][k4 * 4];
            acc[r] = fmaf(a.x, w0, acc[r]);
            acc[r] = fmaf(a.y, w1, acc[r]);
            acc[r] = fmaf(a.z, w2, acc[r]);
            acc[r] = fmaf(a.w, w3, acc[r]);
        }
    }
    float bc = b1[c];
#pragma unroll
    for (int r = 0; r < TILE_R; r++) {
        float v = fmaxf(acc[r] + bc, 0.0f) * s_sout[r];
        g_h1[(size_t)(row0 + r) * HID + c] = v;
    }
}

// ---------------- scatter-add layer 1 (256-wide rows) ----------------
// one warp per edge; lane handles 8 floats (2 x float4) + 8 atomics
__global__ void k_scatter1(const int* __restrict__ src1, const int* __restrict__ dst1, int e1) {
    int e    = (blockIdx.x * blockDim.x + threadIdx.x) >> 5;
    int lane = threadIdx.x & 31;
    if (e >= e1) return;
    int s = src1[e];
    int d = dst1[e];
    const float* sp = g_h1   + (size_t)s * HID + lane * 8;
    float*       dp = g_agg1 + (size_t)d * HID + lane * 8;
    float4 v0 = *(const float4*)(sp);
    float4 v1 = *(const float4*)(sp + 4);
    atomicAdd(dp + 0, v0.x); atomicAdd(dp + 1, v0.y);
    atomicAdd(dp + 2, v0.z); atomicAdd(dp + 3, v0.w);
    atomicAdd(dp + 4, v1.x); atomicAdd(dp + 5, v1.y);
    atomicAdd(dp + 6, v1.z); atomicAdd(dp + 7, v1.w);
}

// ---------------- GEMM2: out = relu((agg1*rsqrt(deg_in1)) @ W2 + b2) -> d_out ------------
// block = 256 threads = 16 rows x 16 cols
__global__ void __launch_bounds__(256) k_gemm2(const float* __restrict__ W2,
                                               const float* __restrict__ b2,
                                               float* __restrict__ out, int n_rows) {
    __shared__ float s_w[HID * OUTD];  // 16 KB
    int tid = threadIdx.x;
#pragma unroll
    for (int i = tid; i < HID * OUTD; i += 256) s_w[i] = W2[i];
    __syncthreads();

    int r_local = tid >> 4;
    int c       = tid & 15;
    int row     = blockIdx.x * 16 + r_local;
    if (row >= n_rows) return;

    const float* a = g_agg1 + (size_t)row * HID;
    float acc = 0.0f;
#pragma unroll 8
    for (int k4 = 0; k4 < HID / 4; k4++) {
        float4 av = *(const float4*)(a + k4 * 4);
        acc = fmaf(av.x, s_w[(k4 * 4 + 0) * OUTD + c], acc);
        acc = fmaf(av.y, s_w[(k4 * 4 + 1) * OUTD + c], acc);
        acc = fmaf(av.z, s_w[(k4 * 4 + 2) * OUTD + c], acc);
        acc = fmaf(av.w, s_w[(k4 * 4 + 3) * OUTD + c], acc);
    }
    float s = rsqrtf(fmaxf((float)g_deg_in1[row], 1.0f));
    out[(size_t)row * OUTD + c] = fmaxf(s * acc + b2[c], 0.0f);
}

// ---------------- labels tail: cast int labels to float ----------------
__global__ void k_labels(const int* __restrict__ labels, float* __restrict__ out,
                         int offset, int n) {
    int i = blockIdx.x * blockDim.x + threadIdx.x;
    if (i < n) out[offset + i] = (float)labels[i];
}

extern "C" void kernel_launch(void* const* d_in, const int* in_sizes, int n_in,
                              void* d_out, int out_size) {
    const int*   user_word = (const int*)  d_in[0];
    const int*   labels    = (const int*)  d_in[1];
    const int*   src0      = (const int*)  d_in[2];
    const int*   dst0      = (const int*)  d_in[3];
    const int*   src1      = (const int*)  d_in[4];
    const int*   dst1      = (const int*)  d_in[5];
    const float* table     = (const float*)d_in[6];
    const float* W1        = (const float*)d_in[7];
    const float* b1        = (const float*)d_in[8];
    const float* W2        = (const float*)d_in[9];
    const float* b2        = (const float*)d_in[10];
    float* out = (float*)d_out;

    const int n_nodes = in_sizes[0] / WORDS_PER_NODE;  // 50000
    const int n_dst1  = in_sizes[1];                   // 5000
    const int e0      = in_sizes[2];                   // 300000
    const int e1      = in_sizes[4];                   // 75000

    // 1. zero accumulators
    {
        int n = N_DST0V * EMB;  // largest region covers all conditions
        k_zero<<<(n + 255) / 256, 256>>>();
    }
    // 2. degrees
    {
        int n = e0 > e1 ? e0 : e1;
        k_degrees<<<(n + 255) / 256, 256>>>(src0, dst0, e0, src1, dst1, e1);
    }
    // 3. embedding gather/mean (+deg_out0 scale)
    k_embed<<<(n_nodes * 32 + 255) / 256, 256>>>(user_word, table, n_nodes);
    // 4. scatter layer 0
    k_scatter0<<<((size_t)e0 * 32 + 255) / 256, 256>>>(src0, dst0, e0);
    // 5. GEMM1 (+relu, +deg_in0 scale on A, +deg_out1 scale on output)
    k_gemm1<<<N_DST0V / TILE_R, 256>>>(W1, b1);
    // 6. scatter layer 1
    k_scatter1<<<((size_t)e1 * 32 + 255) / 256, 256>>>(src1, dst1, e1);
    // 7. GEMM2 (+relu, +deg_in1 scale) -> d_out head
    k_gemm2<<<(n_dst1 + 15) / 16, 256>>>(W2, b2, out, n_dst1);
    // 8. labels tail (as float), if the output buffer carries them
    int feat = n_dst1 * OUTD;
    int nlab = out_size - feat;
    if (nlab > 0) {
        if (nlab > n_dst1) nlab = n_dst1;
        k_labels<<<(nlab + 255) / 256, 256>>>(labels, out, feat, nlab);
    }
}

// round 3
// speedup vs baseline: 1.6807x; 1.6807x over previous
#include <cuda_runtime.h>
#include <cuda_bf16.h>
#include <math.h>

// Problem constants (GCN_83081847374393)
#define N_SRC0   50000
#define N_DST0V  20000
#define N_DST1   5000
#define EMB      128
#define HID      256
#define OUTD     16
#define WORDS_PER_NODE 50   // (10 * 5)
#define E0MAX    300000
#define E1MAX    75000

// -------- scratch (device globals; no allocation allowed) --------
__device__ float g_x0 [(size_t)N_SRC0  * EMB];   // 25.6 MB  (deg_out0-scaled embeddings)
__device__ float g_h1 [(size_t)N_DST0V * HID];   // 20.48 MB (deg_out1-scaled layer-1 output)
__device__ int   g_deg_out0[N_SRC0];
__device__ int   g_deg_in0 [N_DST0V];
__device__ int   g_deg_out1[N_DST0V];
__device__ int   g_deg_in1 [N_DST1];
__device__ int   g_off0[N_DST0V];
__device__ int   g_off1[N_DST1];
__device__ int   g_cnt0[N_DST0V];
__device__ int   g_cnt1[N_DST1];
__device__ int   g_csr0[E0MAX];                  // src ids bucketed by dst (layer 0)
__device__ int   g_csr1[E1MAX];                  // src ids bucketed by dst (layer 1)

// ---------------- zero counters ----------------
__global__ void k_zero() {
    int i = blockIdx.x * blockDim.x + threadIdx.x;
    if (i < N_SRC0)  g_deg_out0[i] = 0;
    if (i < N_DST0V) { g_deg_in0[i] = 0; g_deg_out1[i] = 0; g_cnt0[i] = 0; }
    if (i < N_DST1)  { g_deg_in1[i] = 0; g_cnt1[i] = 0; }
}

// ---------------- degree counting ----------------
__global__ void k_degrees(const int* __restrict__ src0, const int* __restrict__ dst0, int e0,
                          const int* __restrict__ src1, const int* __restrict__ dst1, int e1) {
    int i = blockIdx.x * blockDim.x + threadIdx.x;
    if (i < e0) {
        atomicAdd(&g_deg_out0[src0[i]], 1);
        atomicAdd(&g_deg_in0 [dst0[i]], 1);
    }
    if (i < e1) {
        atomicAdd(&g_deg_out1[src1[i]], 1);
        atomicAdd(&g_deg_in1 [dst1[i]], 1);
    }
}

// ---------------- exclusive scan of in-degrees -> CSR offsets ----------------
// grid=2: block 0 scans deg_in0 (20000), block 1 scans deg_in1 (5000). 512 threads.
__global__ void __launch_bounds__(512) k_scan() {
    __shared__ int s_part[512];
    const int* deg = blockIdx.x ? g_deg_in1 : g_deg_in0;
    int*       off = blockIdx.x ? g_off1    : g_off0;
    int n          = blockIdx.x ? N_DST1    : N_DST0V;
    int tid = threadIdx.x;
    int chunk = (n + 511) / 512;
    int beg = tid * chunk;
    int end = beg + chunk < n ? beg + chunk : n;
    int sum = 0;
    for (int i = beg; i < end; i++) sum += deg[i];
    s_part[tid] = sum;
    __syncthreads();
    // Hillis-Steele inclusive scan
    for (int d = 1; d < 512; d <<= 1) {
        int add = (tid >= d) ? s_part[tid - d] : 0;
        __syncthreads();
        s_part[tid] += add;
        __syncthreads();
    }
    int run = (tid == 0) ? 0 : s_part[tid - 1];
    for (int i = beg; i < end; i++) { off[i] = run; run += deg[i]; }
}

// ---------------- CSR bucket fill ----------------
__global__ void k_csr(const int* __restrict__ src0, const int* __restrict__ dst0, int e0,
                      const int* __restrict__ src1, const int* __restrict__ dst1, int e1) {
    int i = blockIdx.x * blockDim.x + threadIdx.x;
    if (i < e0) {
        int d = dst0[i];
        int p = g_off0[d] + atomicAdd(&g_cnt0[d], 1);
        g_csr0[p] = src0[i];
    }
    if (i < e1) {
        int d = dst1[i];
        int p = g_off1[d] + atomicAdd(&g_cnt1[d], 1);
        g_csr1[p] = src1[i];
    }
}

// ---------------- embedding gather + mean + deg_out0 scaling ----------------
// one warp per node; lane handles 4 consecutive floats (float4)
__global__ void k_embed(const int* __restrict__ uw, const float* __restrict__ table, int n_nodes) {
    int warp = (blockIdx.x * blockDim.x + threadIdx.x) >> 5;
    int lane = threadIdx.x & 31;
    if (warp >= n_nodes) return;
    const int* w = uw + (size_t)warp * WORDS_PER_NODE;
    float ax = 0.f, ay = 0.f, az = 0.f, aw = 0.f;
#pragma unroll 5
    for (int j = 0; j < WORDS_PER_NODE; j++) {
        int idx = __ldg(&w[j]);                       // warp-uniform -> broadcast
        const float4 v = *(const float4*)(table + (size_t)idx * EMB + lane * 4);
        ax += v.x; ay += v.y; az += v.z; aw += v.w;
    }
    float sc = rsqrtf(fmaxf((float)g_deg_out0[warp], 1.0f)) * (1.0f / WORDS_PER_NODE);
    float4 o; o.x = ax * sc; o.y = ay * sc; o.z = az * sc; o.w = aw * sc;
    *(float4*)(g_x0 + (size_t)warp * EMB + lane * 4) = o;
}

// ---------------- fused gather + GEMM1 ----------------
// h1 = relu( (sum_{s in CSR0[row]} x0[s]) * rsqrt(deg_in0) @ W1 + b1 ) * rsqrt(deg_out1)
// block = 256 threads; TILE_R=16 rows; gather phase: warp per row (float4 lanes)
#define TILE_R 16
__global__ void __launch_bounds__(256) k_gemm1(const float* __restrict__ W1,
                                               const float* __restrict__ b1) {
    __shared__ float s_a[TILE_R][EMB];
    __shared__ float s_sout[TILE_R];
    int tid  = threadIdx.x;
    int wid  = tid >> 5;
    int lane = tid & 31;
    int row0 = blockIdx.x * TILE_R;

    // gather + deg_in0 scale into smem A tile
#pragma unroll
    for (int r = wid; r < TILE_R; r += 8) {
        int row = row0 + r;
        int beg = g_off0[row];
        int deg = g_deg_in0[row];
        float ax = 0.f, ay = 0.f, az = 0.f, aw = 0.f;
        for (int j = 0; j < deg; j++) {
            int s = g_csr0[beg + j];                  // lane-uniform -> broadcast
            const float4 v = *(const float4*)(g_x0 + (size_t)s * EMB + lane * 4);
            ax += v.x; ay += v.y; az += v.z; aw += v.w;
        }
        float sc = rsqrtf(fmaxf((float)deg, 1.0f));
        float4 o; o.x = ax * sc; o.y = ay * sc; o.z = az * sc; o.w = aw * sc;
        *(float4*)&s_a[r][lane * 4] = o;
    }
    if (tid < TILE_R) s_sout[tid] = rsqrtf(fmaxf((float)g_deg_out1[row0 + tid], 1.0f));
    __syncthreads();

    int c = tid;  // 0..255 output column
    float acc[TILE_R];
#pragma unroll
    for (int r = 0; r < TILE_R; r++) acc[r] = 0.0f;

#pragma unroll 4
    for (int k4 = 0; k4 < EMB / 4; k4++) {
        float w0 = W1[(k4 * 4 + 0) * HID + c];
        float w1 = W1[(k4 * 4 + 1) * HID + c];
        float w2 = W1[(k4 * 4 + 2) * HID + c];
        float w3 = W1[(k4 * 4 + 3) * HID + c];
#pragma unroll
        for (int r = 0; r < TILE_R; r++) {
            float4 a = *(const float4*)&s_a[r][k4 * 4];
            acc[r] = fmaf(a.x, w0, acc[r]);
            acc[r] = fmaf(a.y, w1, acc[r]);
            acc[r] = fmaf(a.z, w2, acc[r]);
            acc[r] = fmaf(a.w, w3, acc[r]);
        }
    }
    float bc = b1[c];
#pragma unroll
    for (int r = 0; r < TILE_R; r++) {
        float v = fmaxf(acc[r] + bc, 0.0f) * s_sout[r];
        g_h1[(size_t)(row0 + r) * HID + c] = v;
    }
}

// ---------------- fused gather + GEMM2 -> d_out ----------------
// out = relu( (sum_{s in CSR1[row]} h1[s]) * rsqrt(deg_in1) @ W2 + b2 )
// block = 256 threads; 16 rows; gather: warp per row, lane handles 8 floats
__global__ void __launch_bounds__(256) k_gemm2(const float* __restrict__ W2,
                                               const float* __restrict__ b2,
                                               float* __restrict__ out, int n_rows) {
    __shared__ float s_w[HID * OUTD];   // 16 KB
    __shared__ float s_a[16][HID];      // 16 KB
    int tid  = threadIdx.x;
    int wid  = tid >> 5;
    int lane = tid & 31;
    int row0 = blockIdx.x * 16;

#pragma unroll
    for (int i = tid; i < HID * OUTD; i += 256) s_w[i] = W2[i];

#pragma unroll
    for (int r = wid; r < 16; r += 8) {
        int row = row0 + r;
        if (row < n_rows) {
            int beg = g_off1[row];
            int deg = g_deg_in1[row];
            float a0 = 0, a1 = 0, a2 = 0, a3 = 0, a4 = 0, a5 = 0, a6 = 0, a7 = 0;
            for (int j = 0; j < deg; j++) {
                int s = g_csr1[beg + j];
                const float* sp = g_h1 + (size_t)s * HID + lane * 8;
                float4 v0 = *(const float4*)(sp);
                float4 v1 = *(const float4*)(sp + 4);
                a0 += v0.x; a1 += v0.y; a2 += v0.z; a3 += v0.w;
                a4 += v1.x; a5 += v1.y; a6 += v1.z; a7 += v1.w;
            }
            float sc = rsqrtf(fmaxf((float)deg, 1.0f));
            float4 o0; o0.x = a0 * sc; o0.y = a1 * sc; o0.z = a2 * sc; o0.w = a3 * sc;
            float4 o1; o1.x = a4 * sc; o1.y = a5 * sc; o1.z = a6 * sc; o1.w = a7 * sc;
            *(float4*)&s_a[r][lane * 8]     = o0;
            *(float4*)&s_a[r][lane * 8 + 4] = o1;
        }
    }
    __syncthreads();

    int r_local = tid >> 4;
    int c       = tid & 15;
    int row     = row0 + r_local;
    if (row >= n_rows) return;

    float acc = 0.0f;
#pragma unroll 8
    for (int k4 = 0; k4 < HID / 4; k4++) {
        float4 av = *(const float4*)&s_a[r_local][k4 * 4];
        acc = fmaf(av.x, s_w[(k4 * 4 + 0) * OUTD + c], acc);
        acc = fmaf(av.y, s_w[(k4 * 4 + 1) * OUTD + c], acc);
        acc = fmaf(av.z, s_w[(k4 * 4 + 2) * OUTD + c], acc);
        acc = fmaf(av.w, s_w[(k4 * 4 + 3) * OUTD + c], acc);
    }
    out[(size_t)row * OUTD + c] = fmaxf(acc + b2[c], 0.0f);
}

// ---------------- labels tail: cast int labels to float ----------------
__global__ void k_labels(const int* __restrict__ labels, float* __restrict__ out,
                         int offset, int n) {
    int i = blockIdx.x * blockDim.x + threadIdx.x;
    if (i < n) out[offset + i] = (float)labels[i];
}

extern "C" void kernel_launch(void* const* d_in, const int* in_sizes, int n_in,
                              void* d_out, int out_size) {
    const int*   user_word = (const int*)  d_in[0];
    const int*   labels    = (const int*)  d_in[1];
    const int*   src0      = (const int*)  d_in[2];
    const int*   dst0      = (const int*)  d_in[3];
    const int*   src1      = (const int*)  d_in[4];
    const int*   dst1      = (const int*)  d_in[5];
    const float* table     = (const float*)d_in[6];
    const float* W1        = (const float*)d_in[7];
    const float* b1        = (const float*)d_in[8];
    const float* W2        = (const float*)d_in[9];
    const float* b2        = (const float*)d_in[10];
    float* out = (float*)d_out;

    const int n_nodes = in_sizes[0] / WORDS_PER_NODE;  // 50000
    const int n_dst1  = in_sizes[1];                   // 5000
    const int e0      = in_sizes[2];                   // 300000
    const int e1      = in_sizes[4];                   // 75000

    // 1. zero counters
    k_zero<<<(N_SRC0 + 255) / 256, 256>>>();
    // 2. degrees
    {
        int n = e0 > e1 ? e0 : e1;
        k_degrees<<<(n + 255) / 256, 256>>>(src0, dst0, e0, src1, dst1, e1);
    }
    // 3. CSR offsets (exclusive scans)
    k_scan<<<2, 512>>>();
    // 4. CSR bucket fill
    {
        int n = e0 > e1 ? e0 : e1;
        k_csr<<<(n + 255) / 256, 256>>>(src0, dst0, e0, src1, dst1, e1);
    }
    // 5. embedding gather/mean (+deg_out0 scale)
    k_embed<<<(n_nodes * 32 + 255) / 256, 256>>>(user_word, table, n_nodes);
    // 6. fused gather + GEMM1
    k_gemm1<<<N_DST0V / TILE_R, 256>>>(W1, b1);
    // 7. fused gather + GEMM2 -> d_out head
    k_gemm2<<<(n_dst1 + 15) / 16, 256>>>(W2, b2, out, n_dst1);
    // 8. labels tail (as float)
    int feat = n_dst1 * OUTD;
    int nlab = out_size - feat;
    if (nlab > 0) {
        if (nlab > n_dst1) nlab = n_dst1;
        k_labels<<<(nlab + 255) / 256, 256>>>(labels, out, feat, nlab);
    }
}

// round 7
// speedup vs baseline: 1.7999x; 1.0709x over previous
#include <cuda_runtime.h>
#include <cuda_bf16.h>
#include <cuda_fp16.h>
#include <math.h>

// Problem constants (GCN_83081847374393)
#define N_SRC0   50000
#define N_DST0V  20000
#define N_DST1   5000
#define VOCAB    50000
#define EMB      128
#define HID      256
#define OUTD     16
#define WORDS_PER_NODE 50   // (10 * 5)
#define E0MAX    300000
#define E1MAX    75000

// -------- scratch (device globals; no allocation allowed) --------
__device__ __half g_t16[(size_t)VOCAB * EMB];    // 12.8 MB  fp16 word table
__device__ float g_x0 [(size_t)N_SRC0  * EMB];   // 25.6 MB  (deg_out0-scaled embeddings)
__device__ float g_h1 [(size_t)N_DST0V * HID];   // 20.48 MB (deg_out1-scaled layer-1 output)
__device__ int   g_deg_out0[N_SRC0];
__device__ int   g_deg_in0 [N_DST0V];
__device__ int   g_deg_out1[N_DST0V];
__device__ int   g_deg_in1 [N_DST1];
__device__ int   g_off0[N_DST0V];
__device__ int   g_off1[N_DST1];
__device__ int   g_cnt0[N_DST0V];
__device__ int   g_cnt1[N_DST1];
__device__ int   g_csr0[E0MAX];                  // src ids bucketed by dst (layer 0)
__device__ int   g_csr1[E1MAX];                  // src ids bucketed by dst (layer 1)

// ---------------- fp32 -> fp16 table conversion ----------------
// 6.4M elems; each thread converts 4 floats -> 4 halfs (uint2 store)
__global__ void k_tohalf(const float* __restrict__ table) {
    size_t i = ((size_t)blockIdx.x * blockDim.x + threadIdx.x) * 4;
    if (i >= (size_t)VOCAB * EMB) return;
    float4 v = *(const float4*)(table + i);
    __half2 h0 = __floats2half2_rn(v.x, v.y);
    __half2 h1 = __floats2half2_rn(v.z, v.w);
    uint2 o; o.x = *(unsigned*)&h0; o.y = *(unsigned*)&h1;
    *(uint2*)(g_t16 + i) = o;
}

// ---------------- zero counters ----------------
__global__ void k_zero() {
    int i = blockIdx.x * blockDim.x + threadIdx.x;
    if (i < N_SRC0)  g_deg_out0[i] = 0;
    if (i < N_DST0V) { g_deg_in0[i] = 0; g_deg_out1[i] = 0; g_cnt0[i] = 0; }
    if (i < N_DST1)  { g_deg_in1[i] = 0; g_cnt1[i] = 0; }
}

// ---------------- degree counting (4 edges / thread for ILP) ----------------
__global__ void k_degrees(const int* __restrict__ src0, const int* __restrict__ dst0, int e0,
                          const int* __restrict__ src1, const int* __restrict__ dst1, int e1) {
    int base = (blockIdx.x * blockDim.x + threadIdx.x) * 4;
#pragma unroll
    for (int k = 0; k < 4; k++) {
        int i = base + k;
        if (i < e0) {
            atomicAdd(&g_deg_out0[src0[i]], 1);
            atomicAdd(&g_deg_in0 [dst0[i]], 1);
        }
        if (i < e1) {
            atomicAdd(&g_deg_out1[src1[i]], 1);
            atomicAdd(&g_deg_in1 [dst1[i]], 1);
        }
    }
}

// ---------------- exclusive scan of in-degrees -> CSR offsets ----------------
__global__ void __launch_bounds__(512) k_scan() {
    __shared__ int s_part[512];
    const int* deg = blockIdx.x ? g_deg_in1 : g_deg_in0;
    int*       off = blockIdx.x ? g_off1    : g_off0;
    int n          = blockIdx.x ? N_DST1    : N_DST0V;
    int tid = threadIdx.x;
    int chunk = (n + 511) / 512;
    int beg = tid * chunk;
    int end = beg + chunk < n ? beg + chunk : n;
    int sum = 0;
    for (int i = beg; i < end; i++) sum += deg[i];
    s_part[tid] = sum;
    __syncthreads();
    for (int d = 1; d < 512; d <<= 1) {
        int add = (tid >= d) ? s_part[tid - d] : 0;
        __syncthreads();
        s_part[tid] += add;
        __syncthreads();
    }
    int run = (tid == 0) ? 0 : s_part[tid - 1];
    for (int i = beg; i < end; i++) { off[i] = run; run += deg[i]; }
}

// ---------------- CSR bucket fill (4 edges / thread) ----------------
__global__ void k_csr(const int* __restrict__ src0, const int* __restrict__ dst0, int e0,
                      const int* __restrict__ src1, const int* __restrict__ dst1, int e1) {
    int base = (blockIdx.x * blockDim.x + threadIdx.x) * 4;
#pragma unroll
    for (int k = 0; k < 4; k++) {
        int i = base + k;
        if (i < e0) {
            int d = dst0[i];
            int p = g_off0[d] + atomicAdd(&g_cnt0[d], 1);
            g_csr0[p] = src0[i];
        }
        if (i < e1) {
            int d = dst1[i];
            int p = g_off1[d] + atomicAdd(&g_cnt1[d], 1);
            g_csr1[p] = src1[i];
        }
    }
}

// ---------------- embedding gather (fp16 rows) + mean + deg_out0 scaling --------
// one warp per node; lane handles 4 consecutive halfs (uint2 = 2 x half2)
__global__ void k_embed(const int* __restrict__ uw, int n_nodes) {
    int warp = (blockIdx.x * blockDim.x + threadIdx.x) >> 5;
    int lane = threadIdx.x & 31;
    if (warp >= n_nodes) return;
    const int* w = uw + (size_t)warp * WORDS_PER_NODE;
    float ax = 0.f, ay = 0.f, az = 0.f, aw = 0.f;
#pragma unroll 5
    for (int j = 0; j < WORDS_PER_NODE; j++) {
        int idx = __ldg(&w[j]);                          // warp-uniform -> broadcast
        uint2 p = *(const uint2*)(g_t16 + (size_t)idx * EMB + lane * 4);
        float2 f0 = __half22float2(*(__half2*)&p.x);
        float2 f1 = __half22float2(*(__half2*)&p.y);
        ax += f0.x; ay += f0.y; az += f1.x; aw += f1.y;
    }
    float sc = rsqrtf(fmaxf((float)g_deg_out0[warp], 1.0f)) * (1.0f / WORDS_PER_NODE);
    float4 o; o.x = ax * sc; o.y = ay * sc; o.z = az * sc; o.w = aw * sc;
    *(float4*)(g_x0 + (size_t)warp * EMB + lane * 4) = o;
}

// ---------------- fused gather + GEMM1 ----------------
// h1 = relu( (sum_{s in CSR0[row]} x0[s]) * rsqrt(deg_in0) @ W1 + b1 ) * rsqrt(deg_out1)
#define TILE_R 16
__global__ void __launch_bounds__(256) k_gemm1(const float* __restrict__ W1,
                                               const float* __restrict__ b1) {
    __shared__ float s_a[TILE_R][EMB];
    __shared__ float s_sout[TILE_R];
    int tid  = threadIdx.x;
    int wid  = tid >> 5;
    int lane = tid & 31;
    int row0 = blockIdx.x * TILE_R;

    // gather + deg_in0 scale into smem A tile (warp per row)
#pragma unroll
    for (int r = wid; r < TILE_R; r += 8) {
        int row = row0 + r;
        int beg = g_off0[row];
        int deg = g_deg_in0[row];
        float ax = 0.f, ay = 0.f, az = 0.f, aw = 0.f;
        for (int j = 0; j < deg; j++) {
            int s = g_csr0[beg + j];                  // lane-uniform -> broadcast
            const float4 v = *(const float4*)(g_x0 + (size_t)s * EMB + lane * 4);
            ax += v.x; ay += v.y; az += v.z; aw += v.w;
        }
        float sc = rsqrtf(fmaxf((float)deg, 1.0f));
        float4 o; o.x = ax * sc; o.y = ay * sc; o.z = az * sc; o.w = aw * sc;
        *(float4*)&s_a[r][lane * 4] = o;
    }
    if (tid < TILE_R) s_sout[tid] = rsqrtf(fmaxf((float)g_deg_out1[row0 + tid], 1.0f));
    __syncthreads();

    int c = tid;  // 0..255 output column
    float acc[TILE_R];
#pragma unroll
    for (int r = 0; r < TILE_R; r++) acc[r] = 0.0f;

#pragma unroll 4
    for (int k4 = 0; k4 < EMB / 4; k4++) {
        float w0 = W1[(k4 * 4 + 0) * HID + c];
        float w1 = W1[(k4 * 4 + 1) * HID + c];
        float w2 = W1[(k4 * 4 + 2) * HID + c];
        float w3 = W1[(k4 * 4 + 3) * HID + c];
#pragma unroll
        for (int r = 0; r < TILE_R; r++) {
            float4 a = *(const float4*)&s_a[r][k4 * 4];
            acc[r] = fmaf(a.x, w0, acc[r]);
            acc[r] = fmaf(a.y, w1, acc[r]);
            acc[r] = fmaf(a.z, w2, acc[r]);
            acc[r] = fmaf(a.w, w3, acc[r]);
        }
    }
    float bc = b1[c];
#pragma unroll
    for (int r = 0; r < TILE_R; r++) {
        float v = fmaxf(acc[r] + bc, 0.0f) * s_sout[r];
        g_h1[(size_t)(row0 + r) * HID + c] = v;
    }
}

// ---------------- fused gather + GEMM2 -> d_out ----------------
__global__ void __launch_bounds__(256) k_gemm2(const float* __restrict__ W2,
                                               const float* __restrict__ b2,
                                               float* __restrict__ out, int n_rows) {
    __shared__ float s_w[HID * OUTD];   // 16 KB
    __shared__ float s_a[16][HID];      // 16 KB
    int tid  = threadIdx.x;
    int wid  = tid >> 5;
    int lane = tid & 31;
    int row0 = blockIdx.x * 16;

#pragma unroll
    for (int i = tid; i < HID * OUTD; i += 256) s_w[i] = W2[i];

#pragma unroll
    for (int r = wid; r < 16; r += 8) {
        int row = row0 + r;
        if (row < n_rows) {
            int beg = g_off1[row];
            int deg = g_deg_in1[row];
            float a0 = 0, a1 = 0, a2 = 0, a3 = 0, a4 = 0, a5 = 0, a6 = 0, a7 = 0;
            for (int j = 0; j < deg; j++) {
                int s = g_csr1[beg + j];
                const float* sp = g_h1 + (size_t)s * HID + lane * 8;
                float4 v0 = *(const float4*)(sp);
                float4 v1 = *(const float4*)(sp + 4);
                a0 += v0.x; a1 += v0.y; a2 += v0.z; a3 += v0.w;
                a4 += v1.x; a5 += v1.y; a6 += v1.z; a7 += v1.w;
            }
            float sc = rsqrtf(fmaxf((float)deg, 1.0f));
            float4 o0; o0.x = a0 * sc; o0.y = a1 * sc; o0.z = a2 * sc; o0.w = a3 * sc;
            float4 o1; o1.x = a4 * sc; o1.y = a5 * sc; o1.z = a6 * sc; o1.w = a7 * sc;
            *(float4*)&s_a[r][lane * 8]     = o0;
            *(float4*)&s_a[r][lane * 8 + 4] = o1;
        }
    }
    __syncthreads();

    int r_local = tid >> 4;
    int c       = tid & 15;
    int row     = row0 + r_local;
    if (row >= n_rows) return;

    float acc = 0.0f;
#pragma unroll 8
    for (int k4 = 0; k4 < HID / 4; k4++) {
        float4 av = *(const float4*)&s_a[r_local][k4 * 4];
        acc = fmaf(av.x, s_w[(k4 * 4 + 0) * OUTD + c], acc);
        acc = fmaf(av.y, s_w[(k4 * 4 + 1) * OUTD + c], acc);
        acc = fmaf(av.z, s_w[(k4 * 4 + 2) * OUTD + c], acc);
        acc = fmaf(av.w, s_w[(k4 * 4 + 3) * OUTD + c], acc);
    }
    out[(size_t)row * OUTD + c] = fmaxf(acc + b2[c], 0.0f);
}

// ---------------- labels tail: cast int labels to float ----------------
__global__ void k_labels(const int* __restrict__ labels, float* __restrict__ out,
                         int offset, int n) {
    int i = blockIdx.x * blockDim.x + threadIdx.x;
    if (i < n) out[offset + i] = (float)labels[i];
}

extern "C" void kernel_launch(void* const* d_in, const int* in_sizes, int n_in,
                              void* d_out, int out_size) {
    const int*   user_word = (const int*)  d_in[0];
    const int*   labels    = (const int*)  d_in[1];
    const int*   src0      = (const int*)  d_in[2];
    const int*   dst0      = (const int*)  d_in[3];
    const int*   src1      = (const int*)  d_in[4];
    const int*   dst1      = (const int*)  d_in[5];
    const float* table     = (const float*)d_in[6];
    const float* W1        = (const float*)d_in[7];
    const float* b1        = (const float*)d_in[8];
    const float* W2        = (const float*)d_in[9];
    const float* b2        = (const float*)d_in[10];
    float* out = (float*)d_out;

    const int n_nodes = in_sizes[0] / WORDS_PER_NODE;  // 50000
    const int n_dst1  = in_sizes[1];                   // 5000
    const int e0      = in_sizes[2];                   // 300000
    const int e1      = in_sizes[4];                   // 75000

    // 0. fp16 table conversion (overlaps nothing; ~3.5us)
    {
        size_t n4 = ((size_t)VOCAB * EMB) / 4;
        k_tohalf<<<(unsigned)((n4 + 255) / 256), 256>>>(table);
    }
    // 1. zero counters
    k_zero<<<(N_SRC0 + 255) / 256, 256>>>();
    // 2. degrees
    {
        int n = e0 > e1 ? e0 : e1;
        k_degrees<<<(n + 1023) / 1024, 256>>>(src0, dst0, e0, src1, dst1, e1);
    }
    // 3. CSR offsets (exclusive scans)
    k_scan<<<2, 512>>>();
    // 4. CSR bucket fill
    {
        int n = e0 > e1 ? e0 : e1;
        k_csr<<<(n + 1023) / 1024, 256>>>(src0, dst0, e0, src1, dst1, e1);
    }
    // 5. embedding gather/mean from fp16 table (+deg_out0 scale)
    k_embed<<<(n_nodes * 32 + 255) / 256, 256>>>(user_word, n_nodes);
    // 6. fused gather + GEMM1
    k_gemm1<<<N_DST0V / TILE_R, 256>>>(W1, b1);
    // 7. fused gather + GEMM2 -> d_out head
    k_gemm2<<<(n_dst1 + 15) / 16, 256>>>(W2, b2, out, n_dst1);
    // 8. labels tail (as float)
    int feat = n_dst1 * OUTD;
    int nlab = out_size - feat;
    if (nlab > 0) {
        if (nlab > n_dst1) nlab = n_dst1;
        k_labels<<<(nlab + 255) / 256, 256>>>(labels, out, feat, nlab);
    }
}